// round 12
// baseline (speedup 1.0000x reference)
#include <cuda_runtime.h>
#include <cuda_bf16.h>
#include <cstdint>

// Problem constants
#define BB   2048
#define NAG  8
#define ACT  16
#define HIDN 64
#define TILES 1024       // 2 batches per tile (M=256)
#define GRID_MMA 296     // 2 CTAs per SM

// Scratch (__device__ globals: allowed)
__device__ float g_u[BB * NAG * HIDN];     // u[b,g,n]  (4 MB)
__device__ float g_w1aT[HIDN * 128];       // w1aT[k*128 + row]

// ---------------------------------------------------------------------------
__device__ __forceinline__ uint32_t pack_hi(float a, float b) {
    uint32_t r;
    asm("prmt.b32 %0, %1, %2, 0x7632;" : "=r"(r)
        : "r"(__float_as_uint(a)), "r"(__float_as_uint(b)));
    return r;
}
__device__ __forceinline__ uint32_t pack_lo(float a, float b) {
    float ha = __uint_as_float(__float_as_uint(a) & 0xffff0000u);
    float hb = __uint_as_float(__float_as_uint(b) & 0xffff0000u);
    float la = a - ha, lb = b - hb;
    uint32_t r;
    asm("cvt.rn.bf16x2.f32 %0, %1, %2;" : "=r"(r) : "f"(lb), "f"(la));
    return r;
}
__device__ __forceinline__ uint32_t smem_u32(const void* p) {
    uint32_t a;
    asm("{ .reg .u64 t; cvta.to.shared.u64 t, %1; cvt.u32.u64 %0, t; }" : "=r"(a) : "l"(p));
    return a;
}
__device__ __forceinline__ void fma4(float4& acc, float s, const float4 w) {
    acc.x = fmaf(s, w.x, acc.x);
    acc.y = fmaf(s, w.y, acc.y);
    acc.z = fmaf(s, w.z, acc.z);
    acc.w = fmaf(s, w.w, acc.w);
}

#define LDSM_X4(r, addr) \
    asm volatile("ldmatrix.sync.aligned.m8n8.x4.shared.b16 {%0,%1,%2,%3}, [%4];" \
        : "=r"((r)[0]), "=r"((r)[1]), "=r"((r)[2]), "=r"((r)[3]) : "r"(addr))
#define LDSM_X4_T(r, addr) \
    asm volatile("ldmatrix.sync.aligned.m8n8.x4.trans.shared.b16 {%0,%1,%2,%3}, [%4];" \
        : "=r"((r)[0]), "=r"((r)[1]), "=r"((r)[2]), "=r"((r)[3]) : "r"(addr))
#define MMA16816(c, a, b0, b1) \
    asm volatile("mma.sync.aligned.m16n8k16.row.col.f32.bf16.bf16.f32 " \
        "{%0,%1,%2,%3}, {%4,%5,%6,%7}, {%8,%9}, {%0,%1,%2,%3};" \
        : "+f"((c)[0]), "+f"((c)[1]), "+f"((c)[2]), "+f"((c)[3]) \
        : "r"((a)[0]), "r"((a)[1]), "r"((a)[2]), "r"((a)[3]), "r"(b0), "r"(b1))
#define CP_ASYNC16(dst, src) \
    asm volatile("cp.async.cg.shared.global [%0], [%1], 16;" :: "r"(dst), "l"(src) : "memory")
#define CP_COMMIT() asm volatile("cp.async.commit_group;" ::: "memory")
#define CP_WAIT0()  asm volatile("cp.async.wait_group 0;" ::: "memory")

// ---------------------------------------------------------------------------
// Kernel 1: layer-1 factorization (R8 version — measured best).
// ---------------------------------------------------------------------------
__global__ void __launch_bounds__(256) prep_kernel(
    const float* __restrict__ hidden,   // [B, 8, 32]
    const float* __restrict__ actions,  // [B, 8, 16]
    const float* __restrict__ w1,       // [384, 64]
    const float* __restrict__ b1)       // [64]
{
    __shared__ float  sh[8 * 256];
    __shared__ float4 spart[8][16];
    __shared__ int    sidx[64];

    const int tid = threadIdx.x;
    const int b0  = blockIdx.x * 8;
    const float4* __restrict__ w1v = reinterpret_cast<const float4*>(w1);

    if (blockIdx.x == 0) {
        for (int e = tid; e < HIDN * 128; e += 256) {
            const int k   = e >> 7;
            const int row = e & 127;
            const int g   = row >> 4;
            const int a   = row & 15;
            g_w1aT[e] = __ldg(w1 + (g * 48 + 32 + a) * 64 + k);
        }
    }

    {
        const float4* hv = reinterpret_cast<const float4*>(hidden + (size_t)b0 * 256);
        float4* shv = reinterpret_cast<float4*>(sh);
        #pragma unroll
        for (int e = tid; e < 512; e += 256) shv[e] = __ldg(hv + e);
    }

    if (tid < 64) {
        const int bl = tid >> 3, g = tid & 7;
        const float* ag = actions + (size_t)(b0 + bl) * 128 + g * 16;
        float s = 0.f;
        #pragma unroll
        for (int a = 0; a < ACT; ++a) s = fmaf(__ldg(ag + a), (float)a, s);
        sidx[tid] = __float2int_rn(s);
    }
    __syncthreads();

    const int kq = tid >> 7;
    const int bl = (tid >> 4) & 7;
    const int nq = tid & 15;

    float4 acc = make_float4(0.f, 0.f, 0.f, 0.f);
    const float* h0 = sh + bl * 256 + kq * 128;
    #pragma unroll
    for (int j2 = 0; j2 < 4; ++j2) {
        const int j = kq * 4 + j2;
        #pragma unroll
        for (int i4 = 0; i4 < 8; ++i4) {
            const int wrow = j * 48 + i4 * 4;
            const float4 w0  = __ldg(w1v + (wrow + 0) * 16 + nq);
            const float4 w1_ = __ldg(w1v + (wrow + 1) * 16 + nq);
            const float4 w2_ = __ldg(w1v + (wrow + 2) * 16 + nq);
            const float4 w3_ = __ldg(w1v + (wrow + 3) * 16 + nq);
            const float4 h = *reinterpret_cast<const float4*>(h0 + j2 * 32 + i4 * 4);
            fma4(acc, h.x, w0); fma4(acc, h.y, w1_);
            fma4(acc, h.z, w2_); fma4(acc, h.w, w3_);
        }
    }
    if (kq == 1) spart[bl][nq] = acc;
    __syncthreads();

    if (kq == 0) {
        const float4 b1v = __ldg(reinterpret_cast<const float4*>(b1) + nq);
        const float4 p = spart[bl][nq];
        float4 base;
        base.x = acc.x + p.x + b1v.x;
        base.y = acc.y + p.y + b1v.y;
        base.z = acc.z + p.z + b1v.z;
        base.w = acc.w + p.w + b1v.w;

        float4 asum[NAG];
        float4 tot = make_float4(0.f, 0.f, 0.f, 0.f);
        #pragma unroll
        for (int g = 0; g < NAG; ++g) {
            asum[g] = __ldg(w1v + (g * 48 + 32 + sidx[bl * 8 + g]) * 16 + nq);
            tot.x += asum[g].x; tot.y += asum[g].y;
            tot.z += asum[g].z; tot.w += asum[g].w;
        }
        #pragma unroll
        for (int g = 0; g < NAG; ++g) {
            float4 v;
            v.x = base.x + tot.x - asum[g].x;
            v.y = base.y + tot.y - asum[g].y;
            v.z = base.z + tot.z - asum[g].z;
            v.w = base.w + tot.w - asum[g].w;
            *reinterpret_cast<float4*>(
                &g_u[(size_t)((b0 + bl) * NAG + g) * HIDN + nq * 4]) = v;
        }
    }
}

// ---------------------------------------------------------------------------
// Kernel 2: persistent HMMA GEMM, M=256 tiles (2 batches), 256 threads.
// Warp w (0..7) owns rows 32w..32w+31 end-to-end (no cross-warp reduce).
// Per-warp structure identical to R9 (acc[2][8][4], 48 LDSM, 192 HMMA/tile)
// but syncs/u-waits are per 2 batches and 16 warps/SM (2 CTAs).
// A single 64KB buffer (build->sync->mma), B = [W_hi; W_lo] dedup (16KB),
// cp.async double-buffered 4KB u slabs.
// ---------------------------------------------------------------------------
#define SM_A   0         // 65536
#define SM_B   65536     // 16384
#define SM_B2  81920
#define SM_W3  82176
#define SM_U   82432     // 2 x 4096
#define SMEM_SZ 90624

__global__ void __launch_bounds__(256, 2) mma_kernel(
    const float* __restrict__ w2,   // [64, 64] (k-major)
    const float* __restrict__ b2,   // [64]
    const float* __restrict__ w3,   // [64]
    const float* __restrict__ b3,   // [1]
    float* __restrict__ out)        // [B, 128]
{
    extern __shared__ __align__(16) char dsm[];
    const uint32_t smAddr = smem_u32(dsm);
    const uint32_t smA = smAddr + SM_A;
    const uint32_t smB = smAddr + SM_B;
    const uint32_t smU = smAddr + SM_U;
    float* sb2 = reinterpret_cast<float*>(dsm + SM_B2);
    float* sw3 = reinterpret_cast<float*>(dsm + SM_W3);

    const int tid  = threadIdx.x;
    const int wid  = tid >> 5;
    const int lane = tid & 31;

    if (tid < 64) {
        sb2[tid] = __ldg(b2 + tid);
        sw3[tid] = __ldg(w3 + tid);
    }
    const float b3v = __ldg(b3);

    // prologue: prefetch u slab (2 batches = 4KB) for first tile into buffer 0
    CP_ASYNC16(smU + tid * 16, g_u + (size_t)blockIdx.x * 1024 + tid * 4);
    CP_COMMIT();

    // build B = [W_hi; W_lo] (128 k-rows x 64 n), xor-swizzled
    for (int e = tid; e < 128 * 32; e += 256) {
        const int kk = e >> 5;
        const int nw = e & 31;
        const int k  = kk & 63;
        const float2 f = __ldg(reinterpret_cast<const float2*>(w2 + k * 64 + 2 * nw));
        const uint32_t word = (kk < 64) ? pack_hi(f.x, f.y) : pack_lo(f.x, f.y);
        const int nc = nw >> 2;
        const uint32_t byte = (uint32_t)kk * 128u + (uint32_t)((nc ^ (kk & 7)) << 4)
                            + (uint32_t)((nw & 3) << 2);
        *reinterpret_cast<uint32_t*>(dsm + SM_B + byte) = word;
    }

    // per-lane ldmatrix address precompute
    const int g2  = lane >> 4;
    const int gh  = (lane >> 3) & 1;
    const int lr  = lane & 7;
    const int grp = lane >> 2;
    const int tig = lane & 3;

    uint32_t aBase[2];
    #pragma unroll
    for (int mt = 0; mt < 2; ++mt)
        aBase[mt] = smA + (uint32_t)(32 * wid + 16 * mt + 8 * gh + lr) * 256u;

    const int nadd = lane >> 4;
    const uint32_t bBase = smB + (uint32_t)(8 * ((lane >> 3) & 1) + lr) * 128u;
    uint32_t nxor[4];
    #pragma unroll
    for (int np = 0; np < 4; ++np)
        nxor[np] = (uint32_t)(((2 * np + nadd) ^ lr) << 4);

    // build-phase: one row per thread (256 rows)
    const int row  = tid;
    const int half = row >> 7;              // which batch of the pair
    const int ga   = row & 127;
    const int gq   = ga >> 4;
    const uint32_t rbase = (uint32_t)row * 256u;
    const int rx = row & 7;

    int it = 0;
    for (int t = blockIdx.x; t < TILES; t += GRID_MMA) {
        const int cur = it & 1;

        CP_WAIT0();
        __syncthreads();

        // build A': x1[row,k] = relu(u_s[half,g,k] + w1aT[k,ga])
        const float4* us = reinterpret_cast<const float4*>(dsm + SM_U + cur * 4096)
                         + half * 128 + gq * 16;
        #pragma unroll
        for (int c8 = 0; c8 < 8; ++c8) {
            const int k0 = c8 * 8;
            const float4 u0 = us[c8 * 2];
            const float4 u1 = us[c8 * 2 + 1];
            float x[8];
            x[0] = u0.x; x[1] = u0.y; x[2] = u0.z; x[3] = u0.w;
            x[4] = u1.x; x[5] = u1.y; x[6] = u1.z; x[7] = u1.w;
            #pragma unroll
            for (int j = 0; j < 8; ++j)
                x[j] = fmaxf(x[j] + __ldg(g_w1aT + (k0 + j) * 128 + ga), 0.f);

            uint4 hi4, lo4;
            hi4.x = pack_hi(x[0], x[1]); hi4.y = pack_hi(x[2], x[3]);
            hi4.z = pack_hi(x[4], x[5]); hi4.w = pack_hi(x[6], x[7]);
            lo4.x = pack_lo(x[0], x[1]); lo4.y = pack_lo(x[2], x[3]);
            lo4.z = pack_lo(x[4], x[5]); lo4.w = pack_lo(x[6], x[7]);

            *reinterpret_cast<uint4*>(dsm + SM_A + rbase + ((c8 ^ rx) << 4))       = hi4;
            *reinterpret_cast<uint4*>(dsm + SM_A + rbase + (((8 + c8) ^ rx) << 4)) = lo4;
        }

        // prefetch u slab for the next tile
        {
            int tn = t + GRID_MMA;
            if (tn >= TILES) tn = t;
            CP_ASYNC16(smU + (cur ^ 1) * 4096 + tid * 16,
                       g_u + (size_t)tn * 1024 + tid * 4);
            CP_COMMIT();
        }
        __syncthreads();

        // mma phase: 4 physical k-chunks x 3 split products
        float acc[2][8][4];
        #pragma unroll
        for (int mt = 0; mt < 2; ++mt)
            #pragma unroll
            for (int nt = 0; nt < 8; ++nt)
                #pragma unroll
                for (int q = 0; q < 4; ++q) acc[mt][nt][q] = 0.f;

        #pragma unroll
        for (int kp = 0; kp < 4; ++kp) {
            uint32_t ah[2][4], al[2][4];
            #pragma unroll
            for (int mt = 0; mt < 2; ++mt) {
                LDSM_X4(ah[mt], aBase[mt] + (uint32_t)(((2 * kp + g2) ^ lr) << 4));
                LDSM_X4(al[mt], aBase[mt] + (uint32_t)(((8 + 2 * kp + g2) ^ lr) << 4));
            }
            uint32_t bh[4][4], blo[4][4];
            #pragma unroll
            for (int np = 0; np < 4; ++np) {
                LDSM_X4_T(bh[np],  bBase + (uint32_t)(kp * 2048)       + nxor[np]);
                LDSM_X4_T(blo[np], bBase + (uint32_t)((4 + kp) * 2048) + nxor[np]);
            }
            #pragma unroll
            for (int mt = 0; mt < 2; ++mt) {
                #pragma unroll
                for (int np = 0; np < 4; ++np) {
                    MMA16816(acc[mt][2 * np + 0], ah[mt], bh[np][0],  bh[np][1]);
                    MMA16816(acc[mt][2 * np + 1], ah[mt], bh[np][2],  bh[np][3]);
                    MMA16816(acc[mt][2 * np + 0], al[mt], bh[np][0],  bh[np][1]);
                    MMA16816(acc[mt][2 * np + 1], al[mt], bh[np][2],  bh[np][3]);
                    MMA16816(acc[mt][2 * np + 0], ah[mt], blo[np][0], blo[np][1]);
                    MMA16816(acc[mt][2 * np + 1], ah[mt], blo[np][2], blo[np][3]);
                }
            }
        }

        // epilogue: +b2, relu, dot w3, reduce over tig, store
        const int bo = 2 * t + (wid >> 2);      // this warp's batch
        float o[2][2] = {{0.f, 0.f}, {0.f, 0.f}};
        #pragma unroll
        for (int nt = 0; nt < 8; ++nt) {
            const int col = nt * 8 + 2 * tig;
            const float2 bb = *reinterpret_cast<const float2*>(sb2 + col);
            const float2 ww = *reinterpret_cast<const float2*>(sw3 + col);
            #pragma unroll
            for (int mt = 0; mt < 2; ++mt) {
                o[mt][0] = fmaf(fmaxf(acc[mt][nt][0] + bb.x, 0.f), ww.x, o[mt][0]);
                o[mt][0] = fmaf(fmaxf(acc[mt][nt][1] + bb.y, 0.f), ww.y, o[mt][0]);
                o[mt][1] = fmaf(fmaxf(acc[mt][nt][2] + bb.x, 0.f), ww.x, o[mt][1]);
                o[mt][1] = fmaf(fmaxf(acc[mt][nt][3] + bb.y, 0.f), ww.y, o[mt][1]);
            }
        }
        #pragma unroll
        for (int mt = 0; mt < 2; ++mt) {
            #pragma unroll
            for (int rh = 0; rh < 2; ++rh) {
                float v = o[mt][rh];
                v += __shfl_xor_sync(0xffffffffu, v, 1);
                v += __shfl_xor_sync(0xffffffffu, v, 2);
                if (tig == 0) {
                    const int orow = (32 * wid + 16 * mt + 8 * rh + grp) & 127;
                    out[bo * 128 + orow] = v + b3v;
                }
            }
        }
        ++it;
    }
}

// ---------------------------------------------------------------------------
extern "C" void kernel_launch(void* const* d_in, const int* in_sizes, int n_in,
                              void* d_out, int out_size) {
    const float* hidden  = (const float*)d_in[0];
    const float* actions = (const float*)d_in[1];
    const float* w1      = (const float*)d_in[2];
    const float* b1      = (const float*)d_in[3];
    const float* w2      = (const float*)d_in[4];
    const float* b2      = (const float*)d_in[5];
    const float* w3      = (const float*)d_in[6];
    const float* b3      = (const float*)d_in[7];
    float* out = (float*)d_out;

    cudaFuncSetAttribute(mma_kernel, cudaFuncAttributeMaxDynamicSharedMemorySize, SMEM_SZ);

    prep_kernel<<<BB / 8, 256>>>(hidden, actions, w1, b1);
    mma_kernel<<<GRID_MMA, 256, SMEM_SZ>>>(w2, b2, w3, b3, out);
}

// round 13
// speedup vs baseline: 1.1645x; 1.1645x over previous
#include <cuda_runtime.h>
#include <cuda_bf16.h>
#include <cstdint>

// Problem constants
#define BB   2048
#define NAG  8
#define ACT  16
#define HIDN 64
#define GRID_MMA 444   // 3 CTAs per SM (148 SMs)

// Scratch (__device__ globals: allowed)
__device__ float g_w1aT[HIDN * 128];       // w1aT[k*128 + row] = W1[(g*48+32+a)*64 + k]

// ---------------------------------------------------------------------------
__device__ __forceinline__ uint32_t pack_hi(float a, float b) {
    uint32_t r;
    asm("prmt.b32 %0, %1, %2, 0x7632;" : "=r"(r)
        : "r"(__float_as_uint(a)), "r"(__float_as_uint(b)));
    return r;
}
__device__ __forceinline__ uint32_t pack_lo(float a, float b) {
    float ha = __uint_as_float(__float_as_uint(a) & 0xffff0000u);
    float hb = __uint_as_float(__float_as_uint(b) & 0xffff0000u);
    float la = a - ha, lb = b - hb;
    uint32_t r;
    asm("cvt.rn.bf16x2.f32 %0, %1, %2;" : "=r"(r) : "f"(lb), "f"(la));
    return r;
}
__device__ __forceinline__ uint32_t smem_u32(const void* p) {
    uint32_t a;
    asm("{ .reg .u64 t; cvta.to.shared.u64 t, %1; cvt.u32.u64 %0, t; }" : "=r"(a) : "l"(p));
    return a;
}
__device__ __forceinline__ void fma4(float4& acc, float s, const float4 w) {
    acc.x = fmaf(s, w.x, acc.x);
    acc.y = fmaf(s, w.y, acc.y);
    acc.z = fmaf(s, w.z, acc.z);
    acc.w = fmaf(s, w.w, acc.w);
}

#define LDSM_X4(r, addr) \
    asm volatile("ldmatrix.sync.aligned.m8n8.x4.shared.b16 {%0,%1,%2,%3}, [%4];" \
        : "=r"((r)[0]), "=r"((r)[1]), "=r"((r)[2]), "=r"((r)[3]) : "r"(addr))
#define LDSM_X4_T(r, addr) \
    asm volatile("ldmatrix.sync.aligned.m8n8.x4.trans.shared.b16 {%0,%1,%2,%3}, [%4];" \
        : "=r"((r)[0]), "=r"((r)[1]), "=r"((r)[2]), "=r"((r)[3]) : "r"(addr))
#define MMA16816(c, a, b0, b1) \
    asm volatile("mma.sync.aligned.m16n8k16.row.col.f32.bf16.bf16.f32 " \
        "{%0,%1,%2,%3}, {%4,%5,%6,%7}, {%8,%9}, {%0,%1,%2,%3};" \
        : "+f"((c)[0]), "+f"((c)[1]), "+f"((c)[2]), "+f"((c)[3]) \
        : "r"((a)[0]), "r"((a)[1]), "r"((a)[2]), "r"((a)[3]), "r"(b0), "r"(b1))
#define CP_ASYNC16(dst, src) \
    asm volatile("cp.async.cg.shared.global [%0], [%1], 16;" :: "r"(dst), "l"(src) : "memory")
#define CP_COMMIT() asm volatile("cp.async.commit_group;" ::: "memory")
#define CP_WAIT0()  asm volatile("cp.async.wait_group 0;" ::: "memory")

// ---------------------------------------------------------------------------
// Tiny init: column-major action-row table g_w1aT[k*128 + row].
// ---------------------------------------------------------------------------
__global__ void __launch_bounds__(128) init_w1aT(const float* __restrict__ w1) {
    const int e   = blockIdx.x * 128 + threadIdx.x;
    const int k   = e >> 7;
    const int row = e & 127;
    const int g   = row >> 4;
    const int a   = row & 15;
    g_w1aT[e] = __ldg(w1 + (g * 48 + 32 + a) * 64 + k);
}

// ---------------------------------------------------------------------------
// Fused persistent kernel: layer-1 factorization + HMMA GEMM + layers 2/3.
// Per tile b (1 batch, M=128 rows, 128 threads, 3 CTAs/SM):
//  1. cp.async slab (hidden[b] 1KB + actions[b] 512B), double-buffered.
//  2. decode one-hot idx (8 threads) + cooperative base dot:
//     thread (agent kq8, n-quad n4): 32 fma4 -> spart; 16 threads reduce
//     sbase[n] = base + b1 + sum_g w1row(g, idx_g).
//  3. build A': x1[row,k] = relu(sbase[k] + w1aT[k,row] - w1aT[k,rowsub(g)]).
//  4. mma: 4 physical k-chunks x 3 bf16-split products (R9, measured best).
//  5. epilogue: +b2, relu, dot w3, store.
// ---------------------------------------------------------------------------
#define SM_A     0        // 32768
#define SM_B     32768    // 16384: rows 0-63 = W_hi, 64-127 = W_lo
#define SM_B2    49152    // 256
#define SM_W3    49408    // 256
#define SM_PART  49664    // 2048: spart[8][16] float4
#define SM_SBASE 51712    // 256:  sbase4[16]
#define SM_SIDX  51968    // 32:   sidx[8]
#define SM_SLAB  52000    // 2 x 1536 (hidden 1024 + actions 512)
#define SMEM_SZ  55168

__global__ void __launch_bounds__(128, 3) mma_kernel(
    const float* __restrict__ hidden,   // [B, 8, 32]
    const float* __restrict__ actions,  // [B, 8, 16]
    const float* __restrict__ w1,       // [384, 64]
    const float* __restrict__ b1,       // [64]
    const float* __restrict__ w2,       // [64, 64]
    const float* __restrict__ b2,       // [64]
    const float* __restrict__ w3,       // [64]
    const float* __restrict__ b3,       // [1]
    float* __restrict__ out)            // [B, 128]
{
    extern __shared__ __align__(16) char dsm[];
    const uint32_t smAddr = smem_u32(dsm);
    const uint32_t smA    = smAddr + SM_A;
    const uint32_t smB    = smAddr + SM_B;
    const uint32_t smSlab = smAddr + SM_SLAB;
    float*  sb2    = reinterpret_cast<float*>(dsm + SM_B2);
    float*  sw3    = reinterpret_cast<float*>(dsm + SM_W3);
    float4* spart  = reinterpret_cast<float4*>(dsm + SM_PART);   // [8][16]
    float4* sbase4 = reinterpret_cast<float4*>(dsm + SM_SBASE);  // [16]
    int*    sidx   = reinterpret_cast<int*>(dsm + SM_SIDX);      // [8]

    const int tid  = threadIdx.x;
    const int w    = tid >> 5;
    const int lane = tid & 31;
    const float4* __restrict__ w1v = reinterpret_cast<const float4*>(w1);

    if (tid < 64) {
        sb2[tid] = __ldg(b2 + tid);
        sw3[tid] = __ldg(w3 + tid);
    }
    const float b3v = __ldg(b3);

    // prologue: prefetch slab for first tile into buffer 0
    if (tid < 64)
        CP_ASYNC16(smSlab + tid * 16, hidden + (size_t)blockIdx.x * 256 + tid * 4);
    else if (tid < 96)
        CP_ASYNC16(smSlab + 1024 + (tid - 64) * 16,
                   actions + (size_t)blockIdx.x * 128 + (tid - 64) * 4);
    CP_COMMIT();

    // build B = [W_hi; W_lo] (128 k-rows x 64 n), xor-swizzled
    for (int e = tid; e < 128 * 32; e += 128) {
        const int kk = e >> 5;
        const int nw = e & 31;
        const int k  = kk & 63;
        const float2 f = __ldg(reinterpret_cast<const float2*>(w2 + k * 64 + 2 * nw));
        const uint32_t word = (kk < 64) ? pack_hi(f.x, f.y) : pack_lo(f.x, f.y);
        const int nc = nw >> 2;
        const uint32_t byte = (uint32_t)kk * 128u + (uint32_t)((nc ^ (kk & 7)) << 4)
                            + (uint32_t)((nw & 3) << 2);
        *reinterpret_cast<uint32_t*>(dsm + SM_B + byte) = word;
    }

    // per-lane ldmatrix address precompute
    const int g2  = lane >> 4;
    const int gh  = (lane >> 3) & 1;
    const int lr  = lane & 7;
    const int grp = lane >> 2;
    const int tig = lane & 3;

    uint32_t aBase[2];
    #pragma unroll
    for (int mt = 0; mt < 2; ++mt)
        aBase[mt] = smA + (uint32_t)(32 * w + 16 * mt + 8 * gh + lr) * 256u;

    const int nadd = lane >> 4;
    const uint32_t bBase = smB + (uint32_t)(8 * ((lane >> 3) & 1) + lr) * 128u;
    uint32_t nxor[4];
    #pragma unroll
    for (int np = 0; np < 4; ++np)
        nxor[np] = (uint32_t)(((2 * np + nadd) ^ lr) << 4);

    const int row = tid;
    const int gq  = row >> 4;
    const uint32_t rbase = (uint32_t)row * 256u;
    const int rx  = row & 7;
    const int kq8 = tid >> 4;      // agent for base dot
    const int n4  = tid & 15;      // n-quad for base dot

    int it = 0;
    for (int b = blockIdx.x; b < BB; b += GRID_MMA) {
        const int cur = it & 1;

        CP_WAIT0();
        __syncthreads();

        const float* hs  = reinterpret_cast<const float*>(dsm + SM_SLAB + cur * 1536);
        const float* as_ = hs + 256;

        // one-hot decode (exact: actions are {0.0, 1.0})
        if (tid < 8) {
            float s = 0.f;
            #pragma unroll
            for (int a = 0; a < ACT; ++a) s = fmaf(as_[tid * 16 + a], (float)a, s);
            sidx[tid] = __float2int_rn(s);
        }

        // base partial: agent kq8, n-quad n4 (32 fma4 each)
        float4 accb = make_float4(0.f, 0.f, 0.f, 0.f);
        #pragma unroll
        for (int i = 0; i < 32; ++i) {
            const float h = hs[kq8 * 32 + i];
            fma4(accb, h, __ldg(w1v + (kq8 * 48 + i) * 16 + n4));
        }
        spart[kq8 * 16 + n4] = accb;
        __syncthreads();

        // reduce: sbase = sum partials + b1 + sum_g w1row(g, idx_g)
        if (tid < 16) {
            float4 s = spart[tid];
            #pragma unroll
            for (int q = 1; q < 8; ++q) {
                const float4 p = spart[q * 16 + tid];
                s.x += p.x; s.y += p.y; s.z += p.z; s.w += p.w;
            }
            const float4 bv = __ldg(reinterpret_cast<const float4*>(b1) + tid);
            s.x += bv.x; s.y += bv.y; s.z += bv.z; s.w += bv.w;
            #pragma unroll
            for (int g = 0; g < NAG; ++g) {
                const float4 av = __ldg(w1v + (g * 48 + 32 + sidx[g]) * 16 + tid);
                s.x += av.x; s.y += av.y; s.z += av.z; s.w += av.w;
            }
            sbase4[tid] = s;
        }
        __syncthreads();

        const int rowsub = gq * 16 + sidx[gq];

        // build A': x1[row,k] = relu(sbase[k] + w1aT[k,row] - w1aT[k,rowsub])
        #pragma unroll
        for (int c8 = 0; c8 < 8; ++c8) {
            const int k0 = c8 * 8;
            const float4 s0 = sbase4[c8 * 2];
            const float4 s1 = sbase4[c8 * 2 + 1];
            float x[8];
            x[0] = s0.x; x[1] = s0.y; x[2] = s0.z; x[3] = s0.w;
            x[4] = s1.x; x[5] = s1.y; x[6] = s1.z; x[7] = s1.w;
            #pragma unroll
            for (int j = 0; j < 8; ++j) {
                const int k = k0 + j;
                x[j] = fmaxf(x[j] + __ldg(g_w1aT + k * 128 + row)
                                  - __ldg(g_w1aT + k * 128 + rowsub), 0.f);
            }

            uint4 hi4, lo4;
            hi4.x = pack_hi(x[0], x[1]); hi4.y = pack_hi(x[2], x[3]);
            hi4.z = pack_hi(x[4], x[5]); hi4.w = pack_hi(x[6], x[7]);
            lo4.x = pack_lo(x[0], x[1]); lo4.y = pack_lo(x[2], x[3]);
            lo4.z = pack_lo(x[4], x[5]); lo4.w = pack_lo(x[6], x[7]);

            *reinterpret_cast<uint4*>(dsm + SM_A + rbase + ((c8 ^ rx) << 4))       = hi4;
            *reinterpret_cast<uint4*>(dsm + SM_A + rbase + (((8 + c8) ^ rx) << 4)) = lo4;
        }

        // prefetch slab for the next tile
        {
            int bn = b + GRID_MMA;
            if (bn >= BB) bn = b;
            if (tid < 64)
                CP_ASYNC16(smSlab + (cur ^ 1) * 1536 + tid * 16,
                           hidden + (size_t)bn * 256 + tid * 4);
            else if (tid < 96)
                CP_ASYNC16(smSlab + (cur ^ 1) * 1536 + 1024 + (tid - 64) * 16,
                           actions + (size_t)bn * 128 + (tid - 64) * 4);
            CP_COMMIT();
        }
        __syncthreads();

        // mma phase: 4 physical k-chunks x 3 split products (R9, measured best)
        float acc[2][8][4];
        #pragma unroll
        for (int mt = 0; mt < 2; ++mt)
            #pragma unroll
            for (int nt = 0; nt < 8; ++nt)
                #pragma unroll
                for (int q = 0; q < 4; ++q) acc[mt][nt][q] = 0.f;

        #pragma unroll
        for (int kp = 0; kp < 4; ++kp) {
            uint32_t ah[2][4], al[2][4];
            #pragma unroll
            for (int mt = 0; mt < 2; ++mt) {
                LDSM_X4(ah[mt], aBase[mt] + (uint32_t)(((2 * kp + g2) ^ lr) << 4));
                LDSM_X4(al[mt], aBase[mt] + (uint32_t)(((8 + 2 * kp + g2) ^ lr) << 4));
            }
            uint32_t bh[4][4], blo[4][4];
            #pragma unroll
            for (int np = 0; np < 4; ++np) {
                LDSM_X4_T(bh[np],  bBase + (uint32_t)(kp * 2048)       + nxor[np]);
                LDSM_X4_T(blo[np], bBase + (uint32_t)((4 + kp) * 2048) + nxor[np]);
            }
            #pragma unroll
            for (int mt = 0; mt < 2; ++mt) {
                #pragma unroll
                for (int np = 0; np < 4; ++np) {
                    MMA16816(acc[mt][2 * np + 0], ah[mt], bh[np][0],  bh[np][1]);
                    MMA16816(acc[mt][2 * np + 1], ah[mt], bh[np][2],  bh[np][3]);
                    MMA16816(acc[mt][2 * np + 0], al[mt], bh[np][0],  bh[np][1]);
                    MMA16816(acc[mt][2 * np + 1], al[mt], bh[np][2],  bh[np][3]);
                    MMA16816(acc[mt][2 * np + 0], ah[mt], blo[np][0], blo[np][1]);
                    MMA16816(acc[mt][2 * np + 1], ah[mt], blo[np][2], blo[np][3]);
                }
            }
        }

        // epilogue: +b2, relu, dot w3, reduce over tig, store
        float o[2][2] = {{0.f, 0.f}, {0.f, 0.f}};
        #pragma unroll
        for (int nt = 0; nt < 8; ++nt) {
            const int col = nt * 8 + 2 * tig;
            const float2 bb = *reinterpret_cast<const float2*>(sb2 + col);
            const float2 ww = *reinterpret_cast<const float2*>(sw3 + col);
            #pragma unroll
            for (int mt = 0; mt < 2; ++mt) {
                o[mt][0] = fmaf(fmaxf(acc[mt][nt][0] + bb.x, 0.f), ww.x, o[mt][0]);
                o[mt][0] = fmaf(fmaxf(acc[mt][nt][1] + bb.y, 0.f), ww.y, o[mt][0]);
                o[mt][1] = fmaf(fmaxf(acc[mt][nt][2] + bb.x, 0.f), ww.x, o[mt][1]);
                o[mt][1] = fmaf(fmaxf(acc[mt][nt][3] + bb.y, 0.f), ww.y, o[mt][1]);
            }
        }
        #pragma unroll
        for (int mt = 0; mt < 2; ++mt) {
            #pragma unroll
            for (int rh = 0; rh < 2; ++rh) {
                float v = o[mt][rh];
                v += __shfl_xor_sync(0xffffffffu, v, 1);
                v += __shfl_xor_sync(0xffffffffu, v, 2);
                if (tig == 0) {
                    const int orow = 32 * w + 16 * mt + 8 * rh + grp;
                    out[b * 128 + orow] = v + b3v;
                }
            }
        }
        ++it;
    }
}

// ---------------------------------------------------------------------------
extern "C" void kernel_launch(void* const* d_in, const int* in_sizes, int n_in,
                              void* d_out, int out_size) {
    const float* hidden  = (const float*)d_in[0];
    const float* actions = (const float*)d_in[1];
    const float* w1      = (const float*)d_in[2];
    const float* b1      = (const float*)d_in[3];
    const float* w2      = (const float*)d_in[4];
    const float* b2      = (const float*)d_in[5];
    const float* w3      = (const float*)d_in[6];
    const float* b3      = (const float*)d_in[7];
    float* out = (float*)d_out;

    cudaFuncSetAttribute(mma_kernel, cudaFuncAttributeMaxDynamicSharedMemorySize, SMEM_SZ);

    init_w1aT<<<64, 128>>>(w1);
    mma_kernel<<<GRID_MMA, 128, SMEM_SZ>>>(hidden, actions, w1, b1,
                                           w2, b2, w3, b3, out);
}